// round 2
// baseline (speedup 1.0000x reference)
#include <cuda_runtime.h>
#include <cuda_bf16.h>

#define N_CLASSES 64
#define DIM 128
#define QT 256           // queries per block in main kernel
#define ACC_BLK_ROWS 512 // support rows per block in accumulate kernel

// ---------------- device scratch (no allocations allowed) ----------------
__device__ float g_psum[N_CLASSES * DIM];   // class sums
__device__ float g_pcnt[N_CLASSES];         // class counts (float)
__device__ float g_proto[DIM * N_CLASSES];  // prototypes, TRANSPOSED [k][c]
__device__ float g_pnorm[N_CLASSES];        // ||proto_c||^2
__device__ int   g_lbl_is64;                // 1 if labels are int64, else int32

// ---------------- f32x2 packed helpers ----------------
__device__ __forceinline__ unsigned long long pack2(float x, float y) {
    unsigned long long r;
    asm("mov.b64 %0, {%1, %2};" : "=l"(r) : "f"(x), "f"(y));
    return r;
}
__device__ __forceinline__ void unpack2(unsigned long long v, float& x, float& y) {
    asm("mov.b64 {%0, %1}, %2;" : "=f"(x), "=f"(y) : "l"(v));
}
#define FMA2(d, a, b) asm("fma.rn.f32x2 %0, %1, %2, %0;" : "+l"(d) : "l"(a), "l"(b))

// ---------------- kernel 0: zero scratch + detect label dtype ----------------
// If labels are little-endian int64 with values in [0,64), every odd int32
// word of the first 256 labels is 0. With real int32 labels (uniform 0..63),
// P(all 256 odd words == 0) ~ (1/64)^256 ~ 0.
__global__ void k_zero(const int* __restrict__ lbl32) {
    int t = threadIdx.x;
    for (int i = t; i < N_CLASSES * DIM; i += 256) g_psum[i] = 0.0f;
    if (t < N_CLASSES) g_pcnt[t] = 0.0f;

    __shared__ int s_or[256];
    int v = lbl32[2 * t + 1];   // odd words among first 512 int32 words
    s_or[t] = v;
    __syncthreads();
    for (int s = 128; s > 0; s >>= 1) {
        if (t < s) s_or[t] |= s_or[t + s];
        __syncthreads();
    }
    if (t == 0) g_lbl_is64 = (s_or[0] == 0) ? 1 : 0;
}

// ---------------- kernel 2: class-sum accumulate ----------------
// 8 warps/block; warp w owns classes [8w, 8w+8). Register accumulators +
// one global atomic flush per block.
__global__ __launch_bounds__(256) void k_accum(const float* __restrict__ emb,
                                               const int* __restrict__ lbl32,
                                               int nrows) {
    __shared__ int s_lbl[ACC_BLK_ROWS];
    const int base = blockIdx.x * ACC_BLK_ROWS;
    const int tid = threadIdx.x;
    const int w = tid >> 5, lane = tid & 31;
    const int shift = g_lbl_is64;   // 0 -> stride 1, 1 -> stride 2

    for (int i = tid; i < ACC_BLK_ROWS; i += 256) {
        int r = base + i;
        s_lbl[i] = (r < nrows) ? lbl32[r << shift] : -1;
    }
    __syncthreads();

    float acc[8][4];
    int cnt[8];
#pragma unroll
    for (int c = 0; c < 8; c++) {
        cnt[c] = 0;
#pragma unroll
        for (int j = 0; j < 4; j++) acc[c][j] = 0.0f;
    }

    for (int i = 0; i < ACC_BLK_ROWS; i++) {
        int c = s_lbl[i];                      // broadcast LDS -> warp-uniform
        if ((c >> 3) == w) {                   // uniform branch
            const float4 v = *(const float4*)&emb[(base + i) * DIM + lane * 4];
            int cl = c & 7;
#pragma unroll
            for (int cc = 0; cc < 8; cc++) {
                if (cl == cc) {
                    acc[cc][0] += v.x; acc[cc][1] += v.y;
                    acc[cc][2] += v.z; acc[cc][3] += v.w;
                    cnt[cc]++;
                }
            }
        }
    }

#pragma unroll
    for (int cc = 0; cc < 8; cc++) {
        int c = w * 8 + cc;
        float* dst = &g_psum[c * DIM + lane * 4];
        if (cnt[cc]) {
            atomicAdd(dst + 0, acc[cc][0]);
            atomicAdd(dst + 1, acc[cc][1]);
            atomicAdd(dst + 2, acc[cc][2]);
            atomicAdd(dst + 3, acc[cc][3]);
            if (lane == 0) atomicAdd(&g_pcnt[c], (float)cnt[cc]);
        }
    }
}

// ---------------- kernel 3: finalize prototypes ----------------
// one block per class (64 blocks, 128 threads)
__global__ void k_final() {
    const int c = blockIdx.x;
    const int d = threadIdx.x;
    float cn = g_pcnt[c];
    cn = fmaxf(cn, 1.0f);
    float v = g_psum[c * DIM + d] / cn;
    g_proto[d * N_CLASSES + c] = v;   // transposed store

    __shared__ float red[DIM];
    red[d] = v * v;
    __syncthreads();
#pragma unroll
    for (int s = 64; s > 0; s >>= 1) {
        if (d < s) red[d] += red[d + s];
        __syncthreads();
    }
    if (d == 0) g_pnorm[c] = red[0];
}

// ---------------- kernel 4: main — dists + softmax ----------------
// Block: 256 threads, 256 queries (one per thread).
// smem: s_proto[128][64] (32KB), s_pn[64], s_q[256][33] (padded, 33.8KB)
#define SQ_STRIDE 33
#define SMEM_FLOATS (DIM * N_CLASSES + N_CLASSES + QT * SQ_STRIDE)

__global__ __launch_bounds__(256, 2) void k_main(const float* __restrict__ q,
                                                 float* __restrict__ out,
                                                 int nq) {
    extern __shared__ float smem[];
    float* s_proto = smem;                         // [k*64 + c]
    float* s_pn    = smem + DIM * N_CLASSES;       // [64]
    float* s_q     = s_pn + N_CLASSES;             // [256][33]

    const int tid = threadIdx.x;
    const int w = tid >> 5, lane = tid & 31;
    const int q0 = blockIdx.x * QT;

    // stage prototypes (coalesced, float4)
    {
        const float4* src = (const float4*)g_proto;
        float4* dst = (float4*)s_proto;
#pragma unroll
        for (int i = 0; i < (DIM * N_CLASSES / 4) / 256; i++)
            dst[tid + i * 256] = src[tid + i * 256];
        if (tid < N_CLASSES) s_pn[tid] = g_pnorm[tid];
    }

    unsigned long long acc[32];
#pragma unroll
    for (int j = 0; j < 32; j++) acc[j] = 0ULL;
    float qn = 0.0f;

    for (int kc = 0; kc < 4; kc++) {
        __syncthreads();
        // stage 32 dims x 256 queries, coalesced global read, padded smem write
        for (int r = w; r < QT; r += 8) {
            int qi = q0 + r;
            float v = (qi < nq) ? q[qi * DIM + kc * 32 + lane] : 0.0f;
            s_q[r * SQ_STRIDE + lane] = v;
        }
        __syncthreads();

        const float* qrow = &s_q[tid * SQ_STRIDE];
#pragma unroll 8
        for (int kk = 0; kk < 32; kk++) {
            float qk = qrow[kk];
            qn = fmaf(qk, qk, qn);
            unsigned long long qd = pack2(qk, qk);
            const ulonglong2* pr =
                (const ulonglong2*)(s_proto + (kc * 32 + kk) * N_CLASSES);
#pragma unroll
            for (int i = 0; i < 16; i++) {
                ulonglong2 pp = pr[i];          // LDS.128, warp-broadcast
                FMA2(acc[2 * i + 0], pp.x, qd); // classes 4i,4i+1
                FMA2(acc[2 * i + 1], pp.y, qd); // classes 4i+2,4i+3
            }
        }
    }

    // epilogue: dist = sqrt(max(qn + pn - 2*dot, 0)); softmax over 64 classes
    float sum = 0.0f;
#pragma unroll
    for (int j = 0; j < 32; j++) {
        float d0, d1;
        unpack2(acc[j], d0, d1);
        float pn0 = s_pn[2 * j], pn1 = s_pn[2 * j + 1];
        float t0 = sqrtf(fmaxf(fmaf(-2.0f, d0, qn + pn0), 0.0f));
        float t1 = sqrtf(fmaxf(fmaf(-2.0f, d1, qn + pn1), 0.0f));
        float e0 = __expf(-t0);
        float e1 = __expf(-t1);
        sum += e0 + e1;
        acc[j] = pack2(e0, e1);   // reuse registers
    }
    float inv = 1.0f / sum;

    // transposed, coalesced output store through smem (two halves of 32 classes)
#pragma unroll
    for (int half = 0; half < 2; half++) {
        __syncthreads();
#pragma unroll
        for (int p = 0; p < 16; p++) {
            float e0, e1;
            unpack2(acc[half * 16 + p], e0, e1);
            s_q[tid * SQ_STRIDE + 2 * p + 0] = e0 * inv;
            s_q[tid * SQ_STRIDE + 2 * p + 1] = e1 * inv;
        }
        __syncthreads();
        for (int r = w; r < QT; r += 8) {
            int qi = q0 + r;
            if (qi < nq)
                out[qi * N_CLASSES + half * 32 + lane] = s_q[r * SQ_STRIDE + lane];
        }
    }
}

// ---------------- launch ----------------
extern "C" void kernel_launch(void* const* d_in, const int* in_sizes, int n_in,
                              void* d_out, int out_size) {
    const float* emb    = (const float*)d_in[0];
    const int*   lbl32  = (const int*)d_in[1];   // int32 OR int64, auto-detected
    const float* query  = (const float*)d_in[2];
    float*       out    = (float*)d_out;

    const int nsup = in_sizes[1];            // 65536 labels
    const int nq   = in_sizes[2] / DIM;      // 262144 queries

    const size_t smem_bytes = SMEM_FLOATS * sizeof(float); // ~66.8 KB
    cudaFuncSetAttribute(k_main, cudaFuncAttributeMaxDynamicSharedMemorySize,
                         (int)smem_bytes);

    k_zero<<<1, 256>>>(lbl32);
    int ablocks = (nsup + ACC_BLK_ROWS - 1) / ACC_BLK_ROWS;
    k_accum<<<ablocks, 256>>>(emb, lbl32, nsup);
    k_final<<<N_CLASSES, DIM>>>();
    int mblocks = (nq + QT - 1) / QT;
    k_main<<<mblocks, 256, smem_bytes>>>(query, out, nq);
}

// round 4
// speedup vs baseline: 1.5518x; 1.5518x over previous
#include <cuda_runtime.h>
#include <cuda_bf16.h>
#include <cstdint>

#define N_CLASSES 64
#define DIM 128
#define QT 128            // queries per block in MMA kernel
#define ACC_BLK_ROWS 512  // support rows per block in accumulate kernel

// ---------------- device scratch ----------------
__device__ float g_psum[N_CLASSES * DIM];
__device__ float g_pcnt[N_CLASSES];
__device__ float g_pnorm[N_CLASSES];
__device__ int   g_lbl_is64;
// prototypes as bf16 hi/lo, pre-packed in mma.m16n8k16 B-FRAGMENT order:
// [8 ksteps][8 ntiles][32 lanes][2 b32 regs]  (16 KB each)
__device__ unsigned short g_pBf_hi[8192];
__device__ unsigned short g_pBf_lo[8192];

// ---------------- helpers ----------------
__device__ __forceinline__ uint32_t smem_u32(const void* p) {
    uint32_t a;
    asm("{ .reg .u64 t; cvta.to.shared.u64 t, %1; cvt.u32.u64 %0, t; }"
        : "=r"(a) : "l"(p));
    return a;
}
__device__ __forceinline__ uint32_t swz(uint32_t off) { return off ^ ((off >> 3) & 0x70); }

__device__ __forceinline__ void ldmatrix_x4(uint32_t* r, uint32_t addr) {
    asm volatile("ldmatrix.sync.aligned.m8n8.x4.shared.b16 {%0,%1,%2,%3}, [%4];"
                 : "=r"(r[0]), "=r"(r[1]), "=r"(r[2]), "=r"(r[3]) : "r"(addr));
}
__device__ __forceinline__ void mma_bf16(float* d, const uint32_t* a, uint32_t b0, uint32_t b1) {
    asm volatile(
        "mma.sync.aligned.m16n8k16.row.col.f32.bf16.bf16.f32 "
        "{%0,%1,%2,%3}, {%4,%5,%6,%7}, {%8,%9}, {%0,%1,%2,%3};"
        : "+f"(d[0]), "+f"(d[1]), "+f"(d[2]), "+f"(d[3])
        : "r"(a[0]), "r"(a[1]), "r"(a[2]), "r"(a[3]), "r"(b0), "r"(b1));
}

// ---------------- smem layout (bytes) ----------------
#define SM_QN     0                       // 128 x 4
#define SM_PN     512                     // 64 x 4
#define SM_A_HI   1024                    // 2 chunks x 128 rows x 128B = 32768
#define SM_A_LO   (SM_A_HI + 32768)       // 32768
#define SM_BF_HI  (SM_A_LO + 32768)       // 16384
#define SM_BF_LO  (SM_BF_HI + 16384)      // 16384
#define SM_TOTAL  (SM_BF_LO + 16384)      // 99328 -> 2 CTA/SM
#define OUT_STRIDE 68                     // floats; 272B row, 16B aligned

// ================= kernel 0: zero + label dtype detect =================
__global__ void k_zero(const int* __restrict__ lbl32) {
    int t = threadIdx.x;
    for (int i = t; i < N_CLASSES * DIM; i += 256) g_psum[i] = 0.0f;
    if (t < N_CLASSES) g_pcnt[t] = 0.0f;

    __shared__ int s_or[256];
    s_or[t] = lbl32[2 * t + 1];
    __syncthreads();
    for (int s = 128; s > 0; s >>= 1) {
        if (t < s) s_or[t] |= s_or[t + s];
        __syncthreads();
    }
    if (t == 0) g_lbl_is64 = (s_or[0] == 0) ? 1 : 0;
}

// ================= kernel 1: class-sum accumulate =================
__global__ __launch_bounds__(256) void k_accum(const float* __restrict__ emb,
                                               const int* __restrict__ lbl32,
                                               int nrows) {
    __shared__ int s_lbl[ACC_BLK_ROWS];
    const int base = blockIdx.x * ACC_BLK_ROWS;
    const int tid = threadIdx.x;
    const int w = tid >> 5, lane = tid & 31;
    const int shift = g_lbl_is64;

    for (int i = tid; i < ACC_BLK_ROWS; i += 256) {
        int r = base + i;
        s_lbl[i] = (r < nrows) ? lbl32[r << shift] : -1;
    }
    __syncthreads();

    float acc[8][4];
    int cnt[8];
#pragma unroll
    for (int c = 0; c < 8; c++) {
        cnt[c] = 0;
#pragma unroll
        for (int j = 0; j < 4; j++) acc[c][j] = 0.0f;
    }

    for (int i = 0; i < ACC_BLK_ROWS; i++) {
        int c = s_lbl[i];
        if ((c >> 3) == w) {
            const float4 v = *(const float4*)&emb[(size_t)(base + i) * DIM + lane * 4];
            int cl = c & 7;
#pragma unroll
            for (int cc = 0; cc < 8; cc++) {
                if (cl == cc) {
                    acc[cc][0] += v.x; acc[cc][1] += v.y;
                    acc[cc][2] += v.z; acc[cc][3] += v.w;
                    cnt[cc]++;
                }
            }
        }
    }

#pragma unroll
    for (int cc = 0; cc < 8; cc++) {
        int c = w * 8 + cc;
        float* dst = &g_psum[c * DIM + lane * 4];
        if (cnt[cc]) {
            atomicAdd(dst + 0, acc[cc][0]);
            atomicAdd(dst + 1, acc[cc][1]);
            atomicAdd(dst + 2, acc[cc][2]);
            atomicAdd(dst + 3, acc[cc][3]);
            if (lane == 0) atomicAdd(&g_pcnt[c], (float)cnt[cc]);
        }
    }
}

// ================= kernel 2: finalize protos -> B fragments + pnorm =====
// One block per class c (64 blocks, 128 threads = dims).
// B fragment (m16n8k16, col-major): lane L holds b0,b1 = B[2(L%4)+{0,1}][L/4],
// b2,b3 = B[2(L%4)+8+{0,1}][L/4]; pairs packed k-consecutive per b32 reg.
__global__ void k_final() {
    const int c = blockIdx.x;
    const int d = threadIdx.x;
    float cn = fmaxf(g_pcnt[c], 1.0f);
    float v = g_psum[c * DIM + d] / cn;

    __nv_bfloat16 hi = __float2bfloat16(v);
    float fhi = __bfloat162float(hi);
    __nv_bfloat16 lo = __float2bfloat16(v - fhi);
    float vrec = fhi + __bfloat162float(lo);

    int nt = c >> 3;            // ntile
    int ks = d >> 4;            // kstep
    int kp = d & 15;            // k within step
    int lane = 4 * (c & 7) + ((kp & 7) >> 1);
    int reg  = kp >> 3;
    int half = kp & 1;
    int idx = ((((ks * 8 + nt) * 32 + lane) * 2) + reg) * 2 + half;
    g_pBf_hi[idx] = *(unsigned short*)&hi;
    g_pBf_lo[idx] = *(unsigned short*)&lo;

    // pnorm from RECONSTRUCTED proto (consistency with the 3-pass dot)
    __shared__ float red[DIM];
    red[d] = vrec * vrec;
    __syncthreads();
#pragma unroll
    for (int s = 64; s > 0; s >>= 1) {
        if (d < s) red[d] += red[d + s];
        __syncthreads();
    }
    if (d == 0) g_pnorm[c] = red[0];
}

// ================= kernel 3: mma.sync GEMM + softmax =================
__global__ __launch_bounds__(128) void k_mma(const float* __restrict__ q,
                                             float* __restrict__ out, int nq) {
    extern __shared__ char smem[];
    const uint32_t sb = smem_u32(smem);
    const int tid = threadIdx.x;
    const int wid = tid >> 5, lane = tid & 31;
    const int q0 = blockIdx.x * QT;

    // ---- stage A: one query row per thread (hi/lo split, SW128 swizzled) ----
    {
        const int r = tid;
        const int qi = q0 + r;
        float qn = 0.0f;
        const float4* src = (const float4*)&q[(size_t)qi * DIM];
#pragma unroll 4
        for (int l = 0; l < 32; l++) {
            float4 v = (qi < nq) ? src[l] : make_float4(0.f, 0.f, 0.f, 0.f);
            qn = fmaf(v.x, v.x, qn); qn = fmaf(v.y, v.y, qn);
            qn = fmaf(v.z, v.z, qn); qn = fmaf(v.w, v.w, qn);

            __nv_bfloat162 h01 = __float22bfloat162_rn(make_float2(v.x, v.y));
            __nv_bfloat162 h23 = __float22bfloat162_rn(make_float2(v.z, v.w));
            float2 lo01 = make_float2(v.x - __bfloat162float(h01.x),
                                      v.y - __bfloat162float(h01.y));
            float2 lo23 = make_float2(v.z - __bfloat162float(h23.x),
                                      v.w - __bfloat162float(h23.y));
            __nv_bfloat162 l01 = __float22bfloat162_rn(lo01);
            __nv_bfloat162 l23 = __float22bfloat162_rn(lo23);
            uint64_t h64 = (uint64_t)(*(uint32_t*)&h01) | ((uint64_t)(*(uint32_t*)&h23) << 32);
            uint64_t l64 = (uint64_t)(*(uint32_t*)&l01) | ((uint64_t)(*(uint32_t*)&l23) << 32);

            int chunk = l >> 4;                       // k-chunk (64 dims / 128B rows)
            uint32_t off = swz((uint32_t)(r * 128 + (l & 15) * 8));
            *(uint64_t*)(smem + SM_A_HI + chunk * 16384 + off) = h64;
            *(uint64_t*)(smem + SM_A_LO + chunk * 16384 + off) = l64;
        }
        *(float*)(smem + SM_QN + r * 4) = qn;
    }
    // ---- stage B fragments + pnorm (linear copies) ----
    {
        const float4* sh = (const float4*)g_pBf_hi;
        const float4* sl = (const float4*)g_pBf_lo;
        float4* dh = (float4*)(smem + SM_BF_HI);
        float4* dl = (float4*)(smem + SM_BF_LO);
#pragma unroll
        for (int i = 0; i < 8; i++) {
            dh[tid + 128 * i] = sh[tid + 128 * i];
            dl[tid + 128 * i] = sl[tid + 128 * i];
        }
        if (tid < N_CLASSES) *(float*)(smem + SM_PN + tid * 4) = g_pnorm[tid];
    }
    __syncthreads();

    // ---- mma mainloop: 3 passes (qhi*phi, qlo*phi, qhi*plo) ----
    float acc[2][8][4];
#pragma unroll
    for (int mt = 0; mt < 2; mt++)
#pragma unroll
        for (int nt = 0; nt < 8; nt++)
#pragma unroll
            for (int j = 0; j < 4; j++) acc[mt][nt][j] = 0.0f;

    const int mrow = wid * 32 + (lane & 7) + ((lane >> 3) & 1) * 8; // ldmatrix row role
    const int koff = (lane >> 4) * 16;                              // ldmatrix k-half role

#pragma unroll
    for (int pass = 0; pass < 3; pass++) {
        const uint32_t Ab = sb + ((pass == 1) ? SM_A_LO : SM_A_HI);
        const char* Bb = smem + ((pass == 2) ? SM_BF_LO : SM_BF_HI);
#pragma unroll
        for (int ks = 0; ks < 8; ks++) {
            const int chunk = ks >> 2;
            const int kb = (ks & 3) * 32 + koff;
            uint32_t a[2][4];
#pragma unroll
            for (int mt = 0; mt < 2; mt++) {
                uint32_t off = (uint32_t)((mrow + mt * 16) * 128 + kb);
                ldmatrix_x4(a[mt], Ab + chunk * 16384 + swz(off));
            }
            uint2 b[8];
#pragma unroll
            for (int nt = 0; nt < 8; nt++)
                b[nt] = *(const uint2*)(Bb + ((ks * 8 + nt) * 32 + lane) * 8);
#pragma unroll
            for (int mt = 0; mt < 2; mt++)
#pragma unroll
                for (int nt = 0; nt < 8; nt++)
                    mma_bf16(acc[mt][nt], a[mt], b[nt].x, b[nt].y);
        }
    }

    // ---- epilogue: dist -> exp -> softmax (rows L/4 and L/4+8 per mt) ----
    const float* s_pn = (const float*)(smem + SM_PN);
    const float* s_qn = (const float*)(smem + SM_QN);
    float invl[2], invh[2];
#pragma unroll
    for (int mt = 0; mt < 2; mt++) {
        int rl = wid * 32 + mt * 16 + (lane >> 2);
        float qnl = s_qn[rl], qnh = s_qn[rl + 8];
        float sl = 0.f, sh = 0.f;
#pragma unroll
        for (int nt = 0; nt < 8; nt++) {
            int c0 = nt * 8 + (lane & 3) * 2;
            float pn0 = s_pn[c0], pn1 = s_pn[c0 + 1];
            float t0 = sqrtf(fmaxf(fmaf(-2.f, acc[mt][nt][0], qnl + pn0), 0.f));
            float t1 = sqrtf(fmaxf(fmaf(-2.f, acc[mt][nt][1], qnl + pn1), 0.f));
            float t2 = sqrtf(fmaxf(fmaf(-2.f, acc[mt][nt][2], qnh + pn0), 0.f));
            float t3 = sqrtf(fmaxf(fmaf(-2.f, acc[mt][nt][3], qnh + pn1), 0.f));
            float e0 = __expf(-t0), e1 = __expf(-t1);
            float e2 = __expf(-t2), e3 = __expf(-t3);
            sl += e0 + e1; sh += e2 + e3;
            acc[mt][nt][0] = e0; acc[mt][nt][1] = e1;
            acc[mt][nt][2] = e2; acc[mt][nt][3] = e3;
        }
        sl += __shfl_xor_sync(0xffffffffu, sl, 1);
        sl += __shfl_xor_sync(0xffffffffu, sl, 2);
        sh += __shfl_xor_sync(0xffffffffu, sh, 1);
        sh += __shfl_xor_sync(0xffffffffu, sh, 2);
        invl[mt] = 1.0f / sl;
        invh[mt] = 1.0f / sh;
    }

    __syncthreads();   // everyone done reading A smem -> reuse as output staging
    float* sout = (float*)(smem + SM_A_HI);
#pragma unroll
    for (int mt = 0; mt < 2; mt++) {
        int rl = wid * 32 + mt * 16 + (lane >> 2);
#pragma unroll
        for (int nt = 0; nt < 8; nt++) {
            int c0 = nt * 8 + (lane & 3) * 2;
            *(float2*)(sout + rl * OUT_STRIDE + c0) =
                make_float2(acc[mt][nt][0] * invl[mt], acc[mt][nt][1] * invl[mt]);
            *(float2*)(sout + (rl + 8) * OUT_STRIDE + c0) =
                make_float2(acc[mt][nt][2] * invh[mt], acc[mt][nt][3] * invh[mt]);
        }
    }
    __syncthreads();

    // coalesced float4 store: 128 rows x 16 float4
#pragma unroll
    for (int i = 0; i < 16; i++) {
        int lin = i * 128 + tid;
        int m = lin >> 4, c4 = lin & 15;
        int qi = q0 + m;
        if (qi < nq) {
            float4 v = *(const float4*)(sout + m * OUT_STRIDE + c4 * 4);
            *(float4*)&out[(size_t)qi * N_CLASSES + c4 * 4] = v;
        }
    }
}

// ---------------- launch ----------------
extern "C" void kernel_launch(void* const* d_in, const int* in_sizes, int n_in,
                              void* d_out, int out_size) {
    const float* emb   = (const float*)d_in[0];
    const int*   lbl32 = (const int*)d_in[1];   // int32 or int64, auto-detected
    const float* query = (const float*)d_in[2];
    float*       out   = (float*)d_out;

    const int nsup = in_sizes[1];
    const int nq   = in_sizes[2] / DIM;

    cudaFuncSetAttribute(k_mma, cudaFuncAttributeMaxDynamicSharedMemorySize, SM_TOTAL);

    k_zero<<<1, 256>>>(lbl32);
    int ablocks = (nsup + ACC_BLK_ROWS - 1) / ACC_BLK_ROWS;
    k_accum<<<ablocks, 256>>>(emb, lbl32, nsup);
    k_final<<<N_CLASSES, DIM>>>();
    int mblocks = (nq + QT - 1) / QT;
    k_mma<<<mblocks, 128, SM_TOTAL>>>(query, out, nq);
}

// round 5
// speedup vs baseline: 1.8850x; 1.2147x over previous
#include <cuda_runtime.h>
#include <cuda_bf16.h>
#include <cstdint>

#define N_CLASSES 64
#define DIM 128
#define QT 128            // queries per block in MMA kernel

// ---------------- device scratch ----------------
__device__ float g_psum[N_CLASSES * DIM];
__device__ float g_pcnt[N_CLASSES];
__device__ float g_pnorm[N_CLASSES];
__device__ int   g_lbl_is64;
// prototypes as bf16 hi/lo, pre-packed in mma.m16n8k16 B-FRAGMENT order:
// [8 ksteps][8 ntiles][32 lanes][2 b32 regs]  (16 KB each)
__device__ unsigned short g_pBf_hi[8192];
__device__ unsigned short g_pBf_lo[8192];

// ---------------- helpers ----------------
__device__ __forceinline__ uint32_t smem_u32(const void* p) {
    uint32_t a;
    asm("{ .reg .u64 t; cvta.to.shared.u64 t, %1; cvt.u32.u64 %0, t; }"
        : "=r"(a) : "l"(p));
    return a;
}
__device__ __forceinline__ uint32_t swz(uint32_t off) { return off ^ ((off >> 3) & 0x70); }

__device__ __forceinline__ void ldmatrix_x4(uint32_t* r, uint32_t addr) {
    asm volatile("ldmatrix.sync.aligned.m8n8.x4.shared.b16 {%0,%1,%2,%3}, [%4];"
                 : "=r"(r[0]), "=r"(r[1]), "=r"(r[2]), "=r"(r[3]) : "r"(addr));
}
__device__ __forceinline__ void mma_bf16(float* d, const uint32_t* a, uint32_t b0, uint32_t b1) {
    asm volatile(
        "mma.sync.aligned.m16n8k16.row.col.f32.bf16.bf16.f32 "
        "{%0,%1,%2,%3}, {%4,%5,%6,%7}, {%8,%9}, {%0,%1,%2,%3};"
        : "+f"(d[0]), "+f"(d[1]), "+f"(d[2]), "+f"(d[3])
        : "r"(a[0]), "r"(a[1]), "r"(a[2]), "r"(a[3]), "r"(b0), "r"(b1));
}

// ---------------- smem layout for k_mma (bytes) ----------------
#define SM_QN     0                       // 128 x 4
#define SM_PN     512                     // 64 x 4
#define SM_A_HI   1024                    // 2 chunks x 128 rows x 128B = 32768
#define SM_A_LO   (SM_A_HI + 32768)       // 32768
#define SM_BF_HI  (SM_A_LO + 32768)       // 16384
#define SM_BF_LO  (SM_BF_HI + 16384)      // 16384
#define SM_TOTAL  (SM_BF_LO + 16384)      // 99328 -> 2 CTA/SM
#define OUT_STRIDE 68                     // floats; 272B row, 16B aligned

// ================= kernel 0: zero + label dtype detect =================
__global__ void k_zero(const int* __restrict__ lbl32) {
    int t = threadIdx.x;
    for (int i = t; i < N_CLASSES * DIM; i += 256) g_psum[i] = 0.0f;
    if (t < N_CLASSES) g_pcnt[t] = 0.0f;

    __shared__ int s_or[256];
    s_or[t] = lbl32[2 * t + 1];
    __syncthreads();
    for (int s = 128; s > 0; s >>= 1) {
        if (t < s) s_or[t] |= s_or[t + s];
        __syncthreads();
    }
    if (t == 0) g_lbl_is64 = (s_or[0] == 0) ? 1 : 0;
}

// ================= kernel 1: class-sum accumulate (smem atomics) =====
// 256 blocks; block processes a contiguous slab of rows. One warp per row
// per iteration: coalesced 512B row read, 4 shared atomicAdds per lane.
#define ACC_BLOCKS 256
__global__ __launch_bounds__(256) void k_accum(const float* __restrict__ emb,
                                               const int* __restrict__ lbl32,
                                               int nrows) {
    __shared__ float s_acc[N_CLASSES * DIM];  // 32 KB
    __shared__ float s_cnt[N_CLASSES];
    const int tid = threadIdx.x;
    const int w = tid >> 5, lane = tid & 31;
    const int shift = g_lbl_is64;

    for (int i = tid; i < N_CLASSES * DIM; i += 256) s_acc[i] = 0.0f;
    if (tid < N_CLASSES) s_cnt[tid] = 0.0f;
    __syncthreads();

    const int per_blk = (nrows + ACC_BLOCKS - 1) / ACC_BLOCKS;
    const int r0 = blockIdx.x * per_blk;
    const int r1 = min(r0 + per_blk, nrows);

    for (int row = r0 + w; row < r1; row += 8) {
        int c = lbl32[row << shift];          // warp-uniform broadcast load
        float4 v = *(const float4*)&emb[(size_t)row * DIM + lane * 4];
        float* dst = &s_acc[c * DIM + lane * 4];
        atomicAdd(dst + 0, v.x);
        atomicAdd(dst + 1, v.y);
        atomicAdd(dst + 2, v.z);
        atomicAdd(dst + 3, v.w);
        if (lane == 0) atomicAdd(&s_cnt[c], 1.0f);
    }
    __syncthreads();

    for (int i = tid; i < N_CLASSES * DIM; i += 256) {
        float v = s_acc[i];
        if (v != 0.0f) atomicAdd(&g_psum[i], v);
    }
    if (tid < N_CLASSES && s_cnt[tid] != 0.0f) atomicAdd(&g_pcnt[tid], s_cnt[tid]);
}

// ================= kernel 2: finalize protos -> B fragments + pnorm =====
// One block per class c (64 blocks, 128 threads = dims).
__global__ void k_final() {
    const int c = blockIdx.x;
    const int d = threadIdx.x;
    float cn = fmaxf(g_pcnt[c], 1.0f);
    float v = g_psum[c * DIM + d] / cn;

    __nv_bfloat16 hi = __float2bfloat16(v);
    float fhi = __bfloat162float(hi);
    __nv_bfloat16 lo = __float2bfloat16(v - fhi);
    float vrec = fhi + __bfloat162float(lo);

    int nt = c >> 3;            // ntile
    int ks = d >> 4;            // kstep
    int kp = d & 15;            // k within step
    int lane = 4 * (c & 7) + ((kp & 7) >> 1);
    int reg  = kp >> 3;
    int half = kp & 1;
    int idx = ((((ks * 8 + nt) * 32 + lane) * 2) + reg) * 2 + half;
    g_pBf_hi[idx] = *(unsigned short*)&hi;
    g_pBf_lo[idx] = *(unsigned short*)&lo;

    __shared__ float red[DIM];
    red[d] = vrec * vrec;      // pnorm from reconstructed proto (consistency)
    __syncthreads();
#pragma unroll
    for (int s = 64; s > 0; s >>= 1) {
        if (d < s) red[d] += red[d + s];
        __syncthreads();
    }
    if (d == 0) g_pnorm[c] = red[0];
}

// ================= kernel 3: mma.sync GEMM + softmax =================
// 256 threads / 8 warps; warp w owns M-tile rows [16w, 16w+16).
__global__ __launch_bounds__(256, 2) void k_mma(const float* __restrict__ q,
                                                float* __restrict__ out, int nq) {
    extern __shared__ char smem[];
    const uint32_t sb = smem_u32(smem);
    const int tid = threadIdx.x;
    const int wid = tid >> 5, lane = tid & 31;
    const int q0 = blockIdx.x * QT;

    // ---- stage A: warp per row per iter (hi/lo split, SW128 swizzled) ----
    for (int it = 0; it < 16; it++) {
        int r = it * 8 + wid;
        int qi = q0 + r;
        float4 v = (qi < nq) ? *(const float4*)&q[(size_t)qi * DIM + 4 * lane]
                             : make_float4(0.f, 0.f, 0.f, 0.f);
        __nv_bfloat162 h01 = __float22bfloat162_rn(make_float2(v.x, v.y));
        __nv_bfloat162 h23 = __float22bfloat162_rn(make_float2(v.z, v.w));
        float2 lo01 = make_float2(v.x - __bfloat162float(h01.x),
                                  v.y - __bfloat162float(h01.y));
        float2 lo23 = make_float2(v.z - __bfloat162float(h23.x),
                                  v.w - __bfloat162float(h23.y));
        __nv_bfloat162 l01 = __float22bfloat162_rn(lo01);
        __nv_bfloat162 l23 = __float22bfloat162_rn(lo23);
        uint64_t h64 = (uint64_t)(*(uint32_t*)&h01) | ((uint64_t)(*(uint32_t*)&h23) << 32);
        uint64_t l64 = (uint64_t)(*(uint32_t*)&l01) | ((uint64_t)(*(uint32_t*)&l23) << 32);

        int col = 4 * lane;
        int chunk = col >> 6;
        uint32_t off = swz((uint32_t)(r * 128 + (col & 63) * 2));
        *(uint64_t*)(smem + SM_A_HI + chunk * 16384 + off) = h64;
        *(uint64_t*)(smem + SM_A_LO + chunk * 16384 + off) = l64;

        float s = fmaf(v.x, v.x, fmaf(v.y, v.y, fmaf(v.z, v.z, v.w * v.w)));
#pragma unroll
        for (int o = 16; o > 0; o >>= 1) s += __shfl_xor_sync(0xffffffffu, s, o);
        if (lane == 0) *(float*)(smem + SM_QN + r * 4) = s;
    }
    // ---- stage B fragments + pnorm (linear copies) ----
    {
        const float4* sh = (const float4*)g_pBf_hi;
        const float4* sl = (const float4*)g_pBf_lo;
        float4* dh = (float4*)(smem + SM_BF_HI);
        float4* dl = (float4*)(smem + SM_BF_LO);
#pragma unroll
        for (int i = 0; i < 4; i++) {
            dh[tid + 256 * i] = sh[tid + 256 * i];
            dl[tid + 256 * i] = sl[tid + 256 * i];
        }
        if (tid < N_CLASSES) *(float*)(smem + SM_PN + tid * 4) = g_pnorm[tid];
    }
    __syncthreads();

    // ---- mma mainloop: 3 passes (qhi*phi, qlo*phi, qhi*plo) ----
    float acc[8][4];
#pragma unroll
    for (int nt = 0; nt < 8; nt++)
#pragma unroll
        for (int j = 0; j < 4; j++) acc[nt][j] = 0.0f;

    const int mrow = wid * 16 + (lane & 7) + ((lane >> 3) & 1) * 8;
    const int koff = (lane >> 4) * 16;   // bytes: 8 bf16 k-half

#pragma unroll
    for (int pass = 0; pass < 3; pass++) {
        const uint32_t Ab = sb + ((pass == 1) ? SM_A_LO : SM_A_HI);
        const char* Bb = smem + ((pass == 2) ? SM_BF_LO : SM_BF_HI);
#pragma unroll
        for (int ks = 0; ks < 8; ks++) {
            const int chunk = ks >> 2;
            const int kb = (ks & 3) * 32 + koff;
            uint32_t a[4];
            ldmatrix_x4(a, Ab + chunk * 16384 + swz((uint32_t)(mrow * 128 + kb)));
            uint2 b[8];
#pragma unroll
            for (int nt = 0; nt < 8; nt++)
                b[nt] = *(const uint2*)(Bb + ((ks * 8 + nt) * 32 + lane) * 8);
#pragma unroll
            for (int nt = 0; nt < 8; nt++)
                mma_bf16(acc[nt], a, b[nt].x, b[nt].y);
        }
    }

    // ---- epilogue: dist -> exp -> softmax ----
    const float* s_pn = (const float*)(smem + SM_PN);
    const float* s_qn = (const float*)(smem + SM_QN);
    const int rl = wid * 16 + (lane >> 2);
    float qnl = s_qn[rl], qnh = s_qn[rl + 8];
    float sl = 0.f, sh = 0.f;
#pragma unroll
    for (int nt = 0; nt < 8; nt++) {
        int c0 = nt * 8 + (lane & 3) * 2;
        float pn0 = s_pn[c0], pn1 = s_pn[c0 + 1];
        float t0 = sqrtf(fmaxf(fmaf(-2.f, acc[nt][0], qnl + pn0), 0.f));
        float t1 = sqrtf(fmaxf(fmaf(-2.f, acc[nt][1], qnl + pn1), 0.f));
        float t2 = sqrtf(fmaxf(fmaf(-2.f, acc[nt][2], qnh + pn0), 0.f));
        float t3 = sqrtf(fmaxf(fmaf(-2.f, acc[nt][3], qnh + pn1), 0.f));
        float e0 = __expf(-t0), e1 = __expf(-t1);
        float e2 = __expf(-t2), e3 = __expf(-t3);
        sl += e0 + e1; sh += e2 + e3;
        acc[nt][0] = e0; acc[nt][1] = e1;
        acc[nt][2] = e2; acc[nt][3] = e3;
    }
    sl += __shfl_xor_sync(0xffffffffu, sl, 1);
    sl += __shfl_xor_sync(0xffffffffu, sl, 2);
    sh += __shfl_xor_sync(0xffffffffu, sh, 1);
    sh += __shfl_xor_sync(0xffffffffu, sh, 2);
    float invl = 1.0f / sl, invh = 1.0f / sh;

    __syncthreads();   // all warps done reading A smem -> reuse as staging
    float* sout = (float*)(smem + SM_A_HI);
#pragma unroll
    for (int nt = 0; nt < 8; nt++) {
        int c0 = nt * 8 + (lane & 3) * 2;
        *(float2*)(sout + rl * OUT_STRIDE + c0) =
            make_float2(acc[nt][0] * invl, acc[nt][1] * invl);
        *(float2*)(sout + (rl + 8) * OUT_STRIDE + c0) =
            make_float2(acc[nt][2] * invh, acc[nt][3] * invh);
    }
    __syncthreads();

    // coalesced float4 store: 128 rows x 16 float4 = 2048 / 256 thr
#pragma unroll
    for (int i = 0; i < 8; i++) {
        int lin = i * 256 + tid;
        int m = lin >> 4, c4 = lin & 15;
        int qi = q0 + m;
        if (qi < nq) {
            float4 v = *(const float4*)(sout + m * OUT_STRIDE + c4 * 4);
            *(float4*)&out[(size_t)qi * N_CLASSES + c4 * 4] = v;
        }
    }
}

// ---------------- launch ----------------
extern "C" void kernel_launch(void* const* d_in, const int* in_sizes, int n_in,
                              void* d_out, int out_size) {
    const float* emb   = (const float*)d_in[0];
    const int*   lbl32 = (const int*)d_in[1];   // int32 or int64, auto-detected
    const float* query = (const float*)d_in[2];
    float*       out   = (float*)d_out;

    const int nsup = in_sizes[1];
    const int nq   = in_sizes[2] / DIM;

    cudaFuncSetAttribute(k_mma, cudaFuncAttributeMaxDynamicSharedMemorySize, SM_TOTAL);

    k_zero<<<1, 256>>>(lbl32);
    k_accum<<<ACC_BLOCKS, 256>>>(emb, lbl32, nsup);
    k_final<<<N_CLASSES, DIM>>>();
    int mblocks = (nq + QT - 1) / QT;
    k_mma<<<mblocks, 256, SM_TOTAL>>>(query, out, nq);
}

// round 6
// speedup vs baseline: 2.5541x; 1.3550x over previous
#include <cuda_runtime.h>
#include <cuda_fp16.h>
#include <cstdint>

#define N_CLASSES 64
#define DIM 128
#define QT 128            // queries per block in MMA kernel

// ---------------- device scratch ----------------
__device__ float g_psum[N_CLASSES * DIM];
__device__ float g_pcnt[N_CLASSES];
__device__ float g_pnorm[N_CLASSES];
__device__ int   g_lbl_is64;
// prototypes as fp16, pre-packed in mma.m16n8k16 B-FRAGMENT order:
// [8 ksteps][8 ntiles][32 lanes][2 b32 regs]  (16 KB... 8192 halves = 16KB? 8KB)
__device__ unsigned short g_pBf[8192];   // 16 KB bytes? 8192*2B = 16KB. (B frags)

// ---------------- helpers ----------------
__device__ __forceinline__ uint32_t smem_u32(const void* p) {
    uint32_t a;
    asm("{ .reg .u64 t; cvta.to.shared.u64 t, %1; cvt.u32.u64 %0, t; }"
        : "=r"(a) : "l"(p));
    return a;
}
__device__ __forceinline__ uint32_t swz(uint32_t off) { return off ^ ((off >> 3) & 0x70); }

__device__ __forceinline__ void ldmatrix_x4(uint32_t* r, uint32_t addr) {
    asm volatile("ldmatrix.sync.aligned.m8n8.x4.shared.b16 {%0,%1,%2,%3}, [%4];"
                 : "=r"(r[0]), "=r"(r[1]), "=r"(r[2]), "=r"(r[3]) : "r"(addr));
}
__device__ __forceinline__ void mma_f16(float* d, const uint32_t* a, uint32_t b0, uint32_t b1) {
    asm volatile(
        "mma.sync.aligned.m16n8k16.row.col.f32.f16.f16.f32 "
        "{%0,%1,%2,%3}, {%4,%5,%6,%7}, {%8,%9}, {%0,%1,%2,%3};"
        : "+f"(d[0]), "+f"(d[1]), "+f"(d[2]), "+f"(d[3])
        : "r"(a[0]), "r"(a[1]), "r"(a[2]), "r"(a[3]), "r"(b0), "r"(b1));
}

// ---------------- smem layout for k_mma (bytes) ----------------
#define SM_QN     0                       // 128 x 4
#define SM_PN     512                     // 64 x 4
#define SM_A      1024                    // 2 chunks x 128 rows x 128B = 32768
#define SM_B      (SM_A + 32768)          // 16384 (B fragments)
#define SM_TOTAL  (SM_B + 16384)          // 50176 -> 3 CTA/SM (smem 150KB? 3*50=150 <=228 ok)
#define OUT_STRIDE 68                     // floats; 272B row, 16B aligned
// out staging reuses [SM_A, SM_A+49152): needs 128*68*4 = 34816 <= 49152 OK

// ================= kernel 0: zero + label dtype detect =================
__global__ void k_zero(const int* __restrict__ lbl32) {
    int t = threadIdx.x;
    for (int i = t; i < N_CLASSES * DIM; i += 256) g_psum[i] = 0.0f;
    if (t < N_CLASSES) g_pcnt[t] = 0.0f;

    __shared__ int s_or[256];
    s_or[t] = lbl32[2 * t + 1];
    __syncthreads();
    for (int s = 128; s > 0; s >>= 1) {
        if (t < s) s_or[t] |= s_or[t + s];
        __syncthreads();
    }
    if (t == 0) g_lbl_is64 = (s_or[0] == 0) ? 1 : 0;
}

// ================= kernel 1: class-sum accumulate (smem atomics) =====
// 128 blocks; one warp per row per iteration. Lane l owns dims {l, l+32,
// l+64, l+96} -> conflict-free smem atomic banking, coalesced 128B loads.
#define ACC_BLOCKS 128
__global__ __launch_bounds__(256) void k_accum(const float* __restrict__ emb,
                                               const int* __restrict__ lbl32,
                                               int nrows) {
    __shared__ float s_acc[N_CLASSES * DIM];  // 32 KB
    __shared__ float s_cnt[N_CLASSES];
    const int tid = threadIdx.x;
    const int w = tid >> 5, lane = tid & 31;
    const int shift = g_lbl_is64;

    for (int i = tid; i < N_CLASSES * DIM; i += 256) s_acc[i] = 0.0f;
    if (tid < N_CLASSES) s_cnt[tid] = 0.0f;
    __syncthreads();

    const int per_blk = (nrows + ACC_BLOCKS - 1) / ACC_BLOCKS;
    const int r0 = blockIdx.x * per_blk;
    const int r1 = min(r0 + per_blk, nrows);

    for (int row = r0 + w; row < r1; row += 8) {
        int c = lbl32[row << shift];          // warp-uniform broadcast load
        const float* src = &emb[(size_t)row * DIM];
        float v0 = src[lane], v1 = src[lane + 32];
        float v2 = src[lane + 64], v3 = src[lane + 96];
        float* dst = &s_acc[c * DIM];
        atomicAdd(dst + lane,      v0);
        atomicAdd(dst + lane + 32, v1);
        atomicAdd(dst + lane + 64, v2);
        atomicAdd(dst + lane + 96, v3);
        if (lane == 0) atomicAdd(&s_cnt[c], 1.0f);
    }
    __syncthreads();

    for (int i = tid; i < N_CLASSES * DIM; i += 256) {
        float v = s_acc[i];
        if (v != 0.0f) atomicAdd(&g_psum[i], v);
    }
    if (tid < N_CLASSES && s_cnt[tid] != 0.0f) atomicAdd(&g_pcnt[tid], s_cnt[tid]);
}

// ================= kernel 2: finalize protos -> fp16 B fragments + pnorm =====
// One block per class c (64 blocks, 128 threads = dims).
// B fragment (m16n8k16, col-major): lane L, reg r, half h holds
// B[k = 2*(L%4) + 8*r + h][n = L/4].
__global__ void k_final() {
    const int c = blockIdx.x;
    const int d = threadIdx.x;
    float cn = fmaxf(g_pcnt[c], 1.0f);
    float v = g_psum[c * DIM + d] / cn;

    __half hv = __float2half_rn(v);
    float vrec = __half2float(hv);

    int nt = c >> 3;            // ntile
    int ks = d >> 4;            // kstep
    int kp = d & 15;            // k within step
    int lane = 4 * (c & 7) + ((kp & 7) >> 1);
    int reg  = kp >> 3;
    int half = kp & 1;
    int idx = ((((ks * 8 + nt) * 32 + lane) * 2) + reg) * 2 + half;
    g_pBf[idx] = *(unsigned short*)&hv;

    __shared__ float red[DIM];
    red[d] = vrec * vrec;      // pnorm from fp16-reconstructed proto
    __syncthreads();
#pragma unroll
    for (int s = 64; s > 0; s >>= 1) {
        if (d < s) red[d] += red[d + s];
        __syncthreads();
    }
    if (d == 0) g_pnorm[c] = red[0];
}

// ================= kernel 3: single-pass fp16 mma GEMM + softmax ========
// 256 threads / 8 warps; warp w owns M-tile rows [16w, 16w+16).
__global__ __launch_bounds__(256, 3) void k_mma(const float* __restrict__ q,
                                                float* __restrict__ out, int nq) {
    extern __shared__ char smem[];
    const uint32_t sb = smem_u32(smem);
    const int tid = threadIdx.x;
    const int wid = tid >> 5, lane = tid & 31;
    const int q0 = blockIdx.x * QT;

    // ---- stage A: warp per row per iter (fp32 -> fp16, SW128 swizzled) ----
#pragma unroll 4
    for (int it = 0; it < 16; it++) {
        int r = it * 8 + wid;
        int qi = q0 + r;
        float4 v = (qi < nq) ? *(const float4*)&q[(size_t)qi * DIM + 4 * lane]
                             : make_float4(0.f, 0.f, 0.f, 0.f);
        __half2 h01 = __float22half2_rn(make_float2(v.x, v.y));
        __half2 h23 = __float22half2_rn(make_float2(v.z, v.w));
        uint64_t h64 = (uint64_t)(*(uint32_t*)&h01) | ((uint64_t)(*(uint32_t*)&h23) << 32);

        int col = 4 * lane;
        int chunk = col >> 6;
        uint32_t off = swz((uint32_t)(r * 128 + (col & 63) * 2));
        *(uint64_t*)(smem + SM_A + chunk * 16384 + off) = h64;

        float s = fmaf(v.x, v.x, fmaf(v.y, v.y, fmaf(v.z, v.z, v.w * v.w)));
#pragma unroll
        for (int o = 16; o > 0; o >>= 1) s += __shfl_xor_sync(0xffffffffu, s, o);
        if (lane == 0) *(float*)(smem + SM_QN + r * 4) = s;
    }
    // ---- stage B fragments + pnorm (linear copies) ----
    {
        const float4* sh = (const float4*)g_pBf;
        float4* dh = (float4*)(smem + SM_B);
        dh[tid] = sh[tid];
        dh[tid + 256] = sh[tid + 256];
        dh[tid + 512] = sh[tid + 512];
        dh[tid + 768] = sh[tid + 768];
        if (tid < N_CLASSES) *(float*)(smem + SM_PN + tid * 4) = g_pnorm[tid];
    }
    __syncthreads();

    // ---- mma mainloop: single fp16 pass, 8 ksteps ----
    float acc[8][4];
#pragma unroll
    for (int nt = 0; nt < 8; nt++)
#pragma unroll
        for (int j = 0; j < 4; j++) acc[nt][j] = 0.0f;

    const int mrow = wid * 16 + (lane & 7) + ((lane >> 3) & 1) * 8;
    const int koff = (lane >> 4) * 16;   // bytes: 8 fp16 k-half

#pragma unroll
    for (int ks = 0; ks < 8; ks++) {
        const int chunk = ks >> 2;
        const int kb = (ks & 3) * 32 + koff;
        uint32_t a[4];
        ldmatrix_x4(a, sb + SM_A + chunk * 16384 + swz((uint32_t)(mrow * 128 + kb)));
        uint2 b[8];
#pragma unroll
        for (int nt = 0; nt < 8; nt++)
            b[nt] = *(const uint2*)(smem + SM_B + ((ks * 8 + nt) * 32 + lane) * 8);
#pragma unroll
        for (int nt = 0; nt < 8; nt++)
            mma_f16(acc[nt], a, b[nt].x, b[nt].y);
    }

    // ---- epilogue: dist -> exp -> softmax ----
    const float* s_pn = (const float*)(smem + SM_PN);
    const float* s_qn = (const float*)(smem + SM_QN);
    const int rl = wid * 16 + (lane >> 2);
    float qnl = s_qn[rl], qnh = s_qn[rl + 8];
    float sl = 0.f, sh = 0.f;
#pragma unroll
    for (int nt = 0; nt < 8; nt++) {
        int c0 = nt * 8 + (lane & 3) * 2;
        float pn0 = s_pn[c0], pn1 = s_pn[c0 + 1];
        float t0 = sqrtf(fmaxf(fmaf(-2.f, acc[nt][0], qnl + pn0), 0.f));
        float t1 = sqrtf(fmaxf(fmaf(-2.f, acc[nt][1], qnl + pn1), 0.f));
        float t2 = sqrtf(fmaxf(fmaf(-2.f, acc[nt][2], qnh + pn0), 0.f));
        float t3 = sqrtf(fmaxf(fmaf(-2.f, acc[nt][3], qnh + pn1), 0.f));
        float e0 = __expf(-t0), e1 = __expf(-t1);
        float e2 = __expf(-t2), e3 = __expf(-t3);
        sl += e0 + e1; sh += e2 + e3;
        acc[nt][0] = e0; acc[nt][1] = e1;
        acc[nt][2] = e2; acc[nt][3] = e3;
    }
    sl += __shfl_xor_sync(0xffffffffu, sl, 1);
    sl += __shfl_xor_sync(0xffffffffu, sl, 2);
    sh += __shfl_xor_sync(0xffffffffu, sh, 1);
    sh += __shfl_xor_sync(0xffffffffu, sh, 2);
    float invl = 1.0f / sl, invh = 1.0f / sh;

    __syncthreads();   // all warps done reading A/B smem -> reuse as staging
    float* sout = (float*)(smem + SM_A);
#pragma unroll
    for (int nt = 0; nt < 8; nt++) {
        int c0 = nt * 8 + (lane & 3) * 2;
        *(float2*)(sout + rl * OUT_STRIDE + c0) =
            make_float2(acc[nt][0] * invl, acc[nt][1] * invl);
        *(float2*)(sout + (rl + 8) * OUT_STRIDE + c0) =
            make_float2(acc[nt][2] * invh, acc[nt][3] * invh);
    }
    __syncthreads();

    // coalesced float4 store: 128 rows x 16 float4 = 2048 / 256 thr
#pragma unroll
    for (int i = 0; i < 8; i++) {
        int lin = i * 256 + tid;
        int m = lin >> 4, c4 = lin & 15;
        int qi = q0 + m;
        if (qi < nq) {
            float4 v = *(const float4*)(sout + m * OUT_STRIDE + c4 * 4);
            *(float4*)&out[(size_t)qi * N_CLASSES + c4 * 4] = v;
        }
    }
}

// ---------------- launch ----------------
extern "C" void kernel_launch(void* const* d_in, const int* in_sizes, int n_in,
                              void* d_out, int out_size) {
    const float* emb   = (const float*)d_in[0];
    const int*   lbl32 = (const int*)d_in[1];   // int32 or int64, auto-detected
    const float* query = (const float*)d_in[2];
    float*       out   = (float*)d_out;

    const int nsup = in_sizes[1];
    const int nq   = in_sizes[2] / DIM;

    cudaFuncSetAttribute(k_mma, cudaFuncAttributeMaxDynamicSharedMemorySize, SM_TOTAL);

    k_zero<<<1, 256>>>(lbl32);
    k_accum<<<ACC_BLOCKS, 256>>>(emb, lbl32, nsup);
    k_final<<<N_CLASSES, DIM>>>();
    int mblocks = (nq + QT - 1) / QT;
    k_mma<<<mblocks, 256, SM_TOTAL>>>(query, out, nq);
}